// round 1
// baseline (speedup 1.0000x reference)
#include <cuda_runtime.h>
#include <cuda_bf16.h>
#include <math.h>

// Shapes: B=64, N=1024, F=4, H=128. BN = 65536 nodes.
// Inputs (metadata order):
// 0 node_features [64,1024,4]
// 1 adjacency_matrix [64,1024,1024]  (UNUSED by reference)
// 2 W_emb [128,4]   3 b_emb [128]
// 4 W_ih [512,128]  5 b_ih [512]
// 6 W_hh [512,128]  7 b_hh [512]   (W_hh unused: h0 = 0)
// 8 query [1,128]   9 W_attn [128,128]
// 10 v_param [128]  11 W_val [1,128]  12 b_val [1]
// Output: pi [64,1024] then v [64,1]  -> 65600 floats.

#define BN 65536
#define H 128
#define TN 64   // nodes per block in logits kernel

__device__ float g_hx[H];

__device__ __forceinline__ float tanh_fast(float x) {
    float r;
    asm("tanh.approx.f32 %0, %1;" : "=f"(r) : "f"(x));
    return r;
}

// ---------------------------------------------------------------------------
// Kernel 0: hx (batch-invariant LSTM state) + v scalar
// ---------------------------------------------------------------------------
__global__ void k_hx(const float* __restrict__ Wih, const float* __restrict__ bih,
                     const float* __restrict__ bhh, const float* __restrict__ q,
                     const float* __restrict__ Wval, const float* __restrict__ bval,
                     float* __restrict__ out) {
    __shared__ float qs[128];
    __shared__ float gs[512];
    __shared__ float vred[128];
    int t = threadIdx.x;  // 512 threads
    if (t < 128) qs[t] = q[t];
    __syncthreads();
    // gate t = q . W_ih[t,:] + b_ih[t] + b_hh[t]
    float acc = bih[t] + bhh[t];
    const float* w = Wih + t * 128;
    #pragma unroll 8
    for (int k = 0; k < 128; k++) acc += qs[k] * w[k];
    gs[t] = acc;
    __syncthreads();
    if (t < 128) {
        float ig = gs[t];
        float gg = gs[256 + t];
        float og = gs[384 + t];
        float si = 1.f / (1.f + expf(-ig));
        float so = 1.f / (1.f + expf(-og));
        float cx = si * tanhf(gg);
        float hx = so * tanhf(cx);
        g_hx[t] = hx;
        vred[t] = hx * Wval[t];
    }
    __syncthreads();
    for (int s = 64; s > 0; s >>= 1) {
        if (t < s) vred[t] += vred[t + s];
        __syncthreads();
    }
    float v = vred[0] + bval[0];
    if (t < 64) out[BN + t] = v;
}

// ---------------------------------------------------------------------------
// Kernel 1: attention logits for all BN nodes.
//   e[n][k] = relu(x[n] . W_emb[k,:] + b_emb[k])          (k = 0..127)
//   y[n][h] = sum_k e[n][k] * W_attn[h][k]
//   logit[n] = sum_h v_param[h] * tanh(y[n][h] + hx[h])
// Block: 256 threads, 64 nodes. Both GEMM operands fully resident in shared.
// ---------------------------------------------------------------------------
__global__ __launch_bounds__(256, 2)
void k_logits(const float* __restrict__ nf, const float* __restrict__ Wemb,
              const float* __restrict__ bemb, const float* __restrict__ Wattn,
              const float* __restrict__ vparam, float* __restrict__ out) {
    extern __shared__ float sm[];
    float* As  = sm;            // [128][64]  e-values, k-major
    float* Bs  = sm + 8192;     // [128][132] W_attn transposed (padded rows)
    float* wes = Bs + 128 * 132;  // 512
    float* bes = wes + 512;       // 128
    float* hxs = bes + 128;       // 128
    float* vps = hxs + 128;       // 128
    float* red = sm;              // reuse As after GEMM: [64][16]

    int t = threadIdx.x;
    int base = blockIdx.x * TN;

    for (int i = t; i < 512; i += 256) wes[i] = Wemb[i];
    if (t < 128) {
        bes[t] = bemb[t];
        hxs[t] = g_hx[t];
        vps[t] = vparam[t];
    }
    // Transposed W_attn load: Bs[k*132 + h] = Wattn[h*128 + k]
    for (int i = t; i < 16384; i += 256) {
        int h = i >> 7, k = i & 127;
        Bs[k * 132 + h] = Wattn[i];
    }
    __syncthreads();

    // Embedding stage: 4 threads per node, each covers 32 k-values.
    {
        int n = t & 63;
        int part = t >> 6;  // 0..3
        float4 x4 = __ldg((const float4*)nf + (base + n));
        int k0 = part * 32;
        #pragma unroll 8
        for (int k = k0; k < k0 + 32; k++) {
            float e = bes[k] + x4.x * wes[k * 4 + 0] + x4.y * wes[k * 4 + 1]
                             + x4.z * wes[k * 4 + 2] + x4.w * wes[k * 4 + 3];
            As[k * 64 + n] = fmaxf(e, 0.f);
        }
    }
    __syncthreads();

    // Register-tiled GEMM: thread (tn, th) computes nodes n0..n0+3, h0..h0+7.
    int th = t & 15, tn = t >> 4;
    int n0 = tn * 4, h0 = th * 8;
    float acc[4][8];
    #pragma unroll
    for (int i = 0; i < 4; i++)
        #pragma unroll
        for (int j = 0; j < 8; j++) acc[i][j] = 0.f;

    #pragma unroll 4
    for (int k = 0; k < 128; k++) {
        float4 a  = *(const float4*)&As[k * 64 + n0];
        float4 b0 = *(const float4*)&Bs[k * 132 + h0];
        float4 b1 = *(const float4*)&Bs[k * 132 + h0 + 4];
        float av[4] = {a.x, a.y, a.z, a.w};
        float bv[8] = {b0.x, b0.y, b0.z, b0.w, b1.x, b1.y, b1.z, b1.w};
        #pragma unroll
        for (int i = 0; i < 4; i++)
            #pragma unroll
            for (int j = 0; j < 8; j++)
                acc[i][j] += av[i] * bv[j];
    }
    __syncthreads();  // everyone done reading As before red reuses it

    // Epilogue: tanh + v_param dot (partial over this thread's 8 h-values)
    #pragma unroll
    for (int i = 0; i < 4; i++) {
        float s = 0.f;
        #pragma unroll
        for (int j = 0; j < 8; j++) {
            float y = acc[i][j] + hxs[h0 + j];
            s += tanh_fast(y) * vps[h0 + j];
        }
        red[(n0 + i) * 16 + th] = s;
    }
    __syncthreads();
    if (t < 64) {
        float s = 0.f;
        #pragma unroll
        for (int j = 0; j < 16; j++) s += red[t * 16 + j];
        out[base + t] = s;  // raw logit; softmax kernel normalizes in place
    }
}

// ---------------------------------------------------------------------------
// Kernel 2: softmax over N=1024 per batch, in place on out[0..BN).
// ---------------------------------------------------------------------------
__global__ void k_softmax(float* __restrict__ out) {
    __shared__ float red[256];
    int b = blockIdx.x;
    int t = threadIdx.x;  // 256 threads, 4 values each
    float* row = out + b * 1024;
    float4 x = ((const float4*)row)[t];
    float m = fmaxf(fmaxf(x.x, x.y), fmaxf(x.z, x.w));
    red[t] = m;
    __syncthreads();
    for (int s = 128; s > 0; s >>= 1) {
        if (t < s) red[t] = fmaxf(red[t], red[t + s]);
        __syncthreads();
    }
    float M = red[0];
    __syncthreads();
    float e0 = __expf(x.x - M);
    float e1 = __expf(x.y - M);
    float e2 = __expf(x.z - M);
    float e3 = __expf(x.w - M);
    red[t] = e0 + e1 + e2 + e3;
    __syncthreads();
    for (int s = 128; s > 0; s >>= 1) {
        if (t < s) red[t] += red[t + s];
        __syncthreads();
    }
    float inv = 1.f / red[0];
    float4 r;
    r.x = e0 * inv; r.y = e1 * inv; r.z = e2 * inv; r.w = e3 * inv;
    ((float4*)row)[t] = r;
}

// ---------------------------------------------------------------------------
extern "C" void kernel_launch(void* const* d_in, const int* in_sizes, int n_in,
                              void* d_out, int out_size) {
    const float* nf    = (const float*)d_in[0];
    const float* Wemb  = (const float*)d_in[2];
    const float* bemb  = (const float*)d_in[3];
    const float* Wih   = (const float*)d_in[4];
    const float* bih   = (const float*)d_in[5];
    const float* bhh   = (const float*)d_in[7];
    const float* query = (const float*)d_in[8];
    const float* Wattn = (const float*)d_in[9];
    const float* vparam= (const float*)d_in[10];
    const float* Wval  = (const float*)d_in[11];
    const float* bval  = (const float*)d_in[12];
    float* out = (float*)d_out;

    static int smem_set = 0;
    const int smem_bytes = (8192 + 128 * 132 + 512 + 128 + 128 + 128) * 4;
    if (!smem_set) {
        cudaFuncSetAttribute(k_logits, cudaFuncAttributeMaxDynamicSharedMemorySize,
                             smem_bytes);
        smem_set = 1;
    }

    k_hx<<<1, 512>>>(Wih, bih, bhh, query, Wval, bval, out);
    k_logits<<<BN / TN, 256, smem_bytes>>>(nf, Wemb, bemb, Wattn, vparam, out);
    k_softmax<<<64, 256>>>(out);
}

// round 2
// speedup vs baseline: 1.9934x; 1.9934x over previous
#include <cuda_runtime.h>
#include <cuda_bf16.h>
#include <math.h>

// Shapes: B=64, N=1024, F=4, H=128. BN = 65536 nodes.
// Output: pi [64,1024] then v [64,1] -> 65600 floats.
#define BN 65536
#define H 128

__device__ float g_hx[H];

__device__ __forceinline__ float tanh_fast(float x) {
    float r;
    asm("tanh.approx.f32 %0, %1;" : "=f"(r) : "f"(x));
    return r;
}
__device__ __forceinline__ float to_tf32(float x) {
    float r;
    asm("cvt.rna.tf32.f32 %0, %1;" : "=f"(r) : "f"(x));
    return r;
}

// ---------------------------------------------------------------------------
// Kernel 0: hx (batch-invariant LSTM state) + v scalar. 1 block, 512 threads.
// ---------------------------------------------------------------------------
__global__ void k_hx(const float* __restrict__ Wih, const float* __restrict__ bih,
                     const float* __restrict__ bhh, const float* __restrict__ q,
                     const float* __restrict__ Wval, const float* __restrict__ bval,
                     float* __restrict__ out) {
    __shared__ float qs[128];
    __shared__ float gs[512];
    __shared__ float vred[128];
    int t = threadIdx.x;
    if (t < 128) qs[t] = q[t];
    __syncthreads();
    // gate t = q . W_ih[t,:] + b_ih[t] + b_hh[t], vectorized (32 LDG.128 deep)
    const float4* w4 = (const float4*)Wih + t * 32;
    const float4* q4 = (const float4*)qs;
    float4 a4 = make_float4(0.f, 0.f, 0.f, 0.f);
    #pragma unroll
    for (int i = 0; i < 32; i++) {
        float4 w = w4[i];
        float4 qq = q4[i];
        a4.x += w.x * qq.x; a4.y += w.y * qq.y;
        a4.z += w.z * qq.z; a4.w += w.w * qq.w;
    }
    gs[t] = a4.x + a4.y + a4.z + a4.w + bih[t] + bhh[t];
    __syncthreads();
    if (t < 128) {
        float ig = gs[t];
        float gg = gs[256 + t];
        float og = gs[384 + t];
        float si = 1.f / (1.f + __expf(-ig));
        float so = 1.f / (1.f + __expf(-og));
        float cx = si * tanh_fast(gg);
        float hx = so * tanh_fast(cx);
        g_hx[t] = hx;
        vred[t] = hx * Wval[t];
    }
    __syncthreads();
    for (int s = 64; s > 0; s >>= 1) {
        if (t < s) vred[t] += vred[t + s];
        __syncthreads();
    }
    float v = vred[0] + bval[0];
    if (t < 64) out[BN + t] = v;
}

// ---------------------------------------------------------------------------
// Kernel 1: logits via tf32 tensor-core GEMM.
//   C[h][n] = sum_k Wattn[h][k] * e[k][n],  e = relu-embedding (tf32-rounded)
//   logit[n] = sum_h v[h] * tanh(C[h][n] + hx[h])
// Block: 128 threads (4 warps), tile M=128(h) x N=64(nodes) x K=128.
// Warp grid 2x2 -> warp tile 64x32, mma.sync m16n8k8 tf32.
// smem: As[h][k] stride 132 (bank 4g+tc, conflict-free)
//       es[k][n] stride 72  (bank 8tc+g, conflict-free)
// ---------------------------------------------------------------------------
#define AS_STRIDE 132
#define ES_STRIDE 72
#define AS_WORDS (128 * AS_STRIDE)          // 16896
#define ES_WORDS (128 * ES_STRIDE)          // 9216
#define SM_WORDS (AS_WORDS + ES_WORDS + 512 + 128 + 128 + 128 + 128)

__global__ __launch_bounds__(128, 2)
void k_logits(const float* __restrict__ nf, const float* __restrict__ Wemb,
              const float* __restrict__ bemb, const float* __restrict__ Wattn,
              const float* __restrict__ vparam, float* __restrict__ out) {
    extern __shared__ float sm[];
    float* As  = sm;                         // [128][132]
    float* es  = As + AS_WORDS;              // [128][72]
    float* wes = es + ES_WORDS;              // 512 (W_emb)
    float* bes = wes + 512;                  // 128
    float* hxs = bes + 128;                  // 128
    float* vps = hxs + 128;                  // 128
    float* red = vps + 128;                  // [64][2]

    int t = threadIdx.x;
    int base = blockIdx.x * 64;

    // Stage A = W_attn (row-major, tf32-rounded), plus small vectors.
    for (int i = t; i < 16384; i += 128) {
        int h = i >> 7, k = i & 127;
        As[h * AS_STRIDE + k] = to_tf32(Wattn[i]);
    }
    for (int i = t; i < 512; i += 128) wes[i] = Wemb[i];
    if (t < 128) {
        bes[t] = bemb[t];
        hxs[t] = g_hx[t];
        vps[t] = vparam[t];
    }
    __syncthreads();

    // Embedding: e[k][n] = relu(b[k] + x[n].W_emb[k]); 2 threads per node.
    {
        int n = t >> 1;
        int half = t & 1;
        float4 x4 = __ldg((const float4*)nf + (base + n));
        int k0 = half * 64;
        #pragma unroll 8
        for (int k = k0; k < k0 + 64; k++) {
            float e = bes[k] + x4.x * wes[k * 4 + 0] + x4.y * wes[k * 4 + 1]
                             + x4.z * wes[k * 4 + 2] + x4.w * wes[k * 4 + 3];
            es[k * ES_STRIDE + n] = to_tf32(fmaxf(e, 0.f));
        }
    }
    __syncthreads();

    // Tensor-core GEMM.
    int lane = t & 31, w = t >> 5;
    int g = lane >> 2, tc = lane & 3;
    int wm = w >> 1, wn = w & 1;
    int hb = wm * 64;        // warp h base
    int nb = wn * 32;        // warp node base

    float acc[2][4][4];      // wait: 4 m-tiles x 4 n-tiles? -> see below
    // warp tile 64x32: 4 m16 tiles x 4 n8 tiles
    float accr[4][4][4];
    #pragma unroll
    for (int mi = 0; mi < 4; mi++)
        #pragma unroll
        for (int ni = 0; ni < 4; ni++)
            #pragma unroll
            for (int j = 0; j < 4; j++) accr[mi][ni][j] = 0.f;
    (void)acc;

    #pragma unroll 4
    for (int kt = 0; kt < 16; kt++) {
        int kb = kt * 8;
        float af[4][4];
        #pragma unroll
        for (int mi = 0; mi < 4; mi++) {
            int r0 = (hb + mi * 16 + g) * AS_STRIDE + kb + tc;
            af[mi][0] = As[r0];
            af[mi][1] = As[r0 + 8 * AS_STRIDE];
            af[mi][2] = As[r0 + 4];
            af[mi][3] = As[r0 + 8 * AS_STRIDE + 4];
        }
        float bf[4][2];
        #pragma unroll
        for (int ni = 0; ni < 4; ni++) {
            int c0 = (kb + tc) * ES_STRIDE + nb + ni * 8 + g;
            bf[ni][0] = es[c0];
            bf[ni][1] = es[c0 + 4 * ES_STRIDE];
        }
        #pragma unroll
        for (int mi = 0; mi < 4; mi++)
            #pragma unroll
            for (int ni = 0; ni < 4; ni++) {
                asm volatile(
                    "mma.sync.aligned.m16n8k8.row.col.f32.tf32.tf32.f32 "
                    "{%0,%1,%2,%3}, {%4,%5,%6,%7}, {%8,%9}, {%0,%1,%2,%3};"
                    : "+f"(accr[mi][ni][0]), "+f"(accr[mi][ni][1]),
                      "+f"(accr[mi][ni][2]), "+f"(accr[mi][ni][3])
                    : "r"(__float_as_uint(af[mi][0])), "r"(__float_as_uint(af[mi][1])),
                      "r"(__float_as_uint(af[mi][2])), "r"(__float_as_uint(af[mi][3])),
                      "r"(__float_as_uint(bf[ni][0])), "r"(__float_as_uint(bf[ni][1])));
            }
    }

    // Epilogue: tanh + v-dot, reduce over h.
    // acc element (mi,ni,j): row h = hb+mi*16+g (+8 for j>=2), col n = nb+ni*8+2tc+(j&1)
    float pl[4][2];
    #pragma unroll
    for (int ni = 0; ni < 4; ni++)
        #pragma unroll
        for (int j = 0; j < 2; j++) {
            float s = 0.f;
            #pragma unroll
            for (int mi = 0; mi < 4; mi++) {
                int h0 = hb + mi * 16 + g;
                s += tanh_fast(accr[mi][ni][j] + hxs[h0]) * vps[h0];
                s += tanh_fast(accr[mi][ni][j + 2] + hxs[h0 + 8]) * vps[h0 + 8];
            }
            pl[ni][j] = s;
        }
    // reduce over g (lanes differing in bits 2,3,4)
    #pragma unroll
    for (int off = 4; off < 32; off <<= 1)
        #pragma unroll
        for (int ni = 0; ni < 4; ni++)
            #pragma unroll
            for (int j = 0; j < 2; j++)
                pl[ni][j] += __shfl_xor_sync(0xffffffff, pl[ni][j], off);
    if (g == 0) {
        #pragma unroll
        for (int ni = 0; ni < 4; ni++)
            #pragma unroll
            for (int j = 0; j < 2; j++)
                red[(nb + ni * 8 + 2 * tc + j) * 2 + wm] = pl[ni][j];
    }
    __syncthreads();
    if (t < 64) out[base + t] = red[t * 2] + red[t * 2 + 1];
}

// ---------------------------------------------------------------------------
// Kernel 2: softmax over N=1024 per batch, in place.
// ---------------------------------------------------------------------------
__global__ void k_softmax(float* __restrict__ out) {
    __shared__ float red[256];
    int b = blockIdx.x;
    int t = threadIdx.x;
    float* row = out + b * 1024;
    float4 x = ((const float4*)row)[t];
    float m = fmaxf(fmaxf(x.x, x.y), fmaxf(x.z, x.w));
    red[t] = m;
    __syncthreads();
    for (int s = 128; s > 0; s >>= 1) {
        if (t < s) red[t] = fmaxf(red[t], red[t + s]);
        __syncthreads();
    }
    float M = red[0];
    __syncthreads();
    float e0 = __expf(x.x - M);
    float e1 = __expf(x.y - M);
    float e2 = __expf(x.z - M);
    float e3 = __expf(x.w - M);
    red[t] = e0 + e1 + e2 + e3;
    __syncthreads();
    for (int s = 128; s > 0; s >>= 1) {
        if (t < s) red[t] += red[t + s];
        __syncthreads();
    }
    float inv = 1.f / red[0];
    float4 r;
    r.x = e0 * inv; r.y = e1 * inv; r.z = e2 * inv; r.w = e3 * inv;
    ((float4*)row)[t] = r;
}

// ---------------------------------------------------------------------------
extern "C" void kernel_launch(void* const* d_in, const int* in_sizes, int n_in,
                              void* d_out, int out_size) {
    const float* nf     = (const float*)d_in[0];
    const float* Wemb   = (const float*)d_in[2];
    const float* bemb   = (const float*)d_in[3];
    const float* Wih    = (const float*)d_in[4];
    const float* bih    = (const float*)d_in[5];
    const float* bhh    = (const float*)d_in[7];
    const float* query  = (const float*)d_in[8];
    const float* Wattn  = (const float*)d_in[9];
    const float* vparam = (const float*)d_in[10];
    const float* Wval   = (const float*)d_in[11];
    const float* bval   = (const float*)d_in[12];
    float* out = (float*)d_out;

    static int smem_set = 0;
    const int smem_bytes = SM_WORDS * 4;
    if (!smem_set) {
        cudaFuncSetAttribute(k_logits, cudaFuncAttributeMaxDynamicSharedMemorySize,
                             smem_bytes);
        smem_set = 1;
    }

    k_hx<<<1, 512>>>(Wih, bih, bhh, query, Wval, bval, out);
    k_logits<<<BN / 64, 128, smem_bytes>>>(nf, Wemb, bemb, Wattn, vparam, out);
    k_softmax<<<64, 256>>>(out);
}

// round 3
// speedup vs baseline: 3.2741x; 1.6425x over previous
#include <cuda_runtime.h>
#include <cuda_bf16.h>
#include <math.h>

// Shapes: B=64, N=1024, F=4, H=128. BN = 65536 nodes.
// Output: pi [64,1024] then v [64,1] -> 65600 floats.
#define BN 65536
#define H 128
#define NTILES 1024    // node tiles of 64
#define GRID_LOGITS 296

typedef unsigned long long ull;

__device__ float g_hx[H];

__device__ __forceinline__ float tanh_fast(float x) {
    float r;
    asm("tanh.approx.f32 %0, %1;" : "=f"(r) : "f"(x));
    return r;
}
__device__ __forceinline__ float to_tf32(float x) {
    float r;
    asm("cvt.rna.tf32.f32 %0, %1;" : "=f"(r) : "f"(x));
    return r;
}
// ---- packed f32x2 helpers (FFMA2 path ptxas won't auto-emit) ----
__device__ __forceinline__ ull pack2(float lo, float hi) {
    ull r; asm("mov.b64 %0, {%1, %2};" : "=l"(r) : "f"(lo), "f"(hi)); return r;
}
__device__ __forceinline__ void unpack2(ull p, float& lo, float& hi) {
    asm("mov.b64 {%0, %1}, %2;" : "=f"(lo), "=f"(hi) : "l"(p));
}
__device__ __forceinline__ ull fma2(ull a, ull b, ull c) {
    ull r; asm("fma.rn.f32x2 %0, %1, %2, %3;" : "=l"(r) : "l"(a), "l"(b), "l"(c)); return r;
}
__device__ __forceinline__ ull mul2(ull a, ull b) {
    ull r; asm("mul.rn.f32x2 %0, %1, %2;" : "=l"(r) : "l"(a), "l"(b)); return r;
}
__device__ __forceinline__ ull add2(ull a, ull b) {
    ull r; asm("add.rn.f32x2 %0, %1, %2;" : "=l"(r) : "l"(a), "l"(b)); return r;
}

// ---------------------------------------------------------------------------
// Kernel 0: hx (batch-invariant LSTM state) + v scalar. 1 block, 512 threads.
// ---------------------------------------------------------------------------
__global__ void k_hx(const float* __restrict__ Wih, const float* __restrict__ bih,
                     const float* __restrict__ bhh, const float* __restrict__ q,
                     const float* __restrict__ Wval, const float* __restrict__ bval,
                     float* __restrict__ out) {
    __shared__ float qs[128];
    __shared__ float gs[512];
    __shared__ float vred[128];
    int t = threadIdx.x;
    if (t < 128) qs[t] = q[t];
    __syncthreads();
    const float4* w4 = (const float4*)Wih + t * 32;
    const float4* q4 = (const float4*)qs;
    float4 a4 = make_float4(0.f, 0.f, 0.f, 0.f);
    #pragma unroll
    for (int i = 0; i < 32; i++) {
        float4 w = w4[i];
        float4 qq = q4[i];
        a4.x += w.x * qq.x; a4.y += w.y * qq.y;
        a4.z += w.z * qq.z; a4.w += w.w * qq.w;
    }
    gs[t] = a4.x + a4.y + a4.z + a4.w + bih[t] + bhh[t];
    __syncthreads();
    if (t < 128) {
        float ig = gs[t];
        float gg = gs[256 + t];
        float og = gs[384 + t];
        float si = 1.f / (1.f + __expf(-ig));
        float so = 1.f / (1.f + __expf(-og));
        float cx = si * tanh_fast(gg);
        float hx = so * tanh_fast(cx);
        g_hx[t] = hx;
        vred[t] = hx * Wval[t];
    }
    __syncthreads();
    for (int s = 64; s > 0; s >>= 1) {
        if (t < s) vred[t] += vred[t + s];
        __syncthreads();
    }
    float v = vred[0] + bval[0];
    if (t < 64) out[BN + t] = v;
}

// ---------------------------------------------------------------------------
// Kernel 1: logits. tf32 mma GEMM + dual-pipe (MUFU + packed-poly) epilogue.
// Persistent-ish: grid=296, each block stages W_attn ONCE, then grid-strides
// over 1024 node-tiles of 64 nodes.
// ---------------------------------------------------------------------------
#define AS_STRIDE 132
#define ES_STRIDE 72
#define AS_WORDS (128 * AS_STRIDE)          // 16896
#define ES_WORDS (128 * ES_STRIDE)          // 9216
#define SM_WORDS (AS_WORDS + ES_WORDS + 512 + 128 + 128 + 128 + 128)

__global__ __launch_bounds__(128, 2)
void k_logits(const float* __restrict__ nf, const float* __restrict__ Wemb,
              const float* __restrict__ bemb, const float* __restrict__ Wattn,
              const float* __restrict__ vparam, float* __restrict__ out) {
    extern __shared__ float sm[];
    float* As  = sm;                         // [128][132]
    float* es  = As + AS_WORDS;              // [128][72]
    float* wes = es + ES_WORDS;              // 512 (W_emb)
    float* bes = wes + 512;                  // 128
    float* hxs = bes + 128;                  // 128
    float* vps = hxs + 128;                  // 128
    float* red = vps + 128;                  // [64][2]

    int t = threadIdx.x;

    // ---- one-time staging: A = tf32(W_attn), vectorized ----
    for (int i = t * 4; i < 16384; i += 512) {
        float4 w = *(const float4*)(Wattn + i);
        int h = i >> 7, k = i & 127;
        float4 v;
        v.x = to_tf32(w.x); v.y = to_tf32(w.y);
        v.z = to_tf32(w.z); v.w = to_tf32(w.w);
        *(float4*)&As[h * AS_STRIDE + k] = v;
    }
    for (int i = t; i < 512; i += 128) wes[i] = Wemb[i];
    if (t < 128) {
        bes[t] = bemb[t];
        hxs[t] = g_hx[t];
        vps[t] = vparam[t];
    }

    int lane = t & 31, w = t >> 5;
    int g = lane >> 2, tc = lane & 3;
    int wm = w >> 1, wn = w & 1;
    int hb = wm * 64;
    int nb = wn * 32;

    // poly coefficients (deg-7 odd Taylor of tanh), packed
    const ull C3 = pack2(-0.3333333333f, -0.3333333333f);
    const ull C5 = pack2(0.1333333333f, 0.1333333333f);
    const ull C7 = pack2(-0.0539682540f, -0.0539682540f);

    for (int tile = blockIdx.x; tile < NTILES; tile += GRID_LOGITS) {
        int base = tile * 64;
        __syncthreads();   // prior tile done with es/red (also covers staging)

        // Embedding: e[k][n] = tf32(relu(b[k] + x[n].W_emb[k])); 2 thr/node.
        {
            int n = t >> 1;
            int half = t & 1;
            float4 x4 = __ldg((const float4*)nf + (base + n));
            int k0 = half * 64;
            #pragma unroll 8
            for (int k = k0; k < k0 + 64; k++) {
                float e = bes[k] + x4.x * wes[k * 4 + 0] + x4.y * wes[k * 4 + 1]
                                 + x4.z * wes[k * 4 + 2] + x4.w * wes[k * 4 + 3];
                es[k * ES_STRIDE + n] = to_tf32(fmaxf(e, 0.f));
            }
        }
        __syncthreads();

        // ---- tensor-core GEMM: C[h][n], warp tile 64x32 ----
        float accr[4][4][4];
        #pragma unroll
        for (int mi = 0; mi < 4; mi++)
            #pragma unroll
            for (int ni = 0; ni < 4; ni++)
                #pragma unroll
                for (int j = 0; j < 4; j++) accr[mi][ni][j] = 0.f;

        #pragma unroll 4
        for (int kt = 0; kt < 16; kt++) {
            int kb = kt * 8;
            float af[4][4];
            #pragma unroll
            for (int mi = 0; mi < 4; mi++) {
                int r0 = (hb + mi * 16 + g) * AS_STRIDE + kb + tc;
                af[mi][0] = As[r0];
                af[mi][1] = As[r0 + 8 * AS_STRIDE];
                af[mi][2] = As[r0 + 4];
                af[mi][3] = As[r0 + 8 * AS_STRIDE + 4];
            }
            float bf[4][2];
            #pragma unroll
            for (int ni = 0; ni < 4; ni++) {
                int c0 = (kb + tc) * ES_STRIDE + nb + ni * 8 + g;
                bf[ni][0] = es[c0];
                bf[ni][1] = es[c0 + 4 * ES_STRIDE];
            }
            #pragma unroll
            for (int mi = 0; mi < 4; mi++)
                #pragma unroll
                for (int ni = 0; ni < 4; ni++) {
                    asm volatile(
                        "mma.sync.aligned.m16n8k8.row.col.f32.tf32.tf32.f32 "
                        "{%0,%1,%2,%3}, {%4,%5,%6,%7}, {%8,%9}, {%0,%1,%2,%3};"
                        : "+f"(accr[mi][ni][0]), "+f"(accr[mi][ni][1]),
                          "+f"(accr[mi][ni][2]), "+f"(accr[mi][ni][3])
                        : "r"(__float_as_uint(af[mi][0])), "r"(__float_as_uint(af[mi][1])),
                          "r"(__float_as_uint(af[mi][2])), "r"(__float_as_uint(af[mi][3])),
                          "r"(__float_as_uint(bf[ni][0])), "r"(__float_as_uint(bf[ni][1])));
                }
        }

        // ---- dual-pipe epilogue: s2[ni] = packed sum over h of v*tanh(y) ----
        // pair lo/hi = columns n, n+1. mi 0,1 -> MUFU path; mi 2,3 -> packed poly.
        ull s2[4];
        #pragma unroll
        for (int ni = 0; ni < 4; ni++) s2[ni] = pack2(0.f, 0.f);

        #pragma unroll
        for (int mi = 0; mi < 4; mi++) {
            int h0 = hb + mi * 16 + g;
            ull hxa = pack2(hxs[h0], hxs[h0]);
            ull hxb = pack2(hxs[h0 + 8], hxs[h0 + 8]);
            ull va  = pack2(vps[h0], vps[h0]);
            ull vb  = pack2(vps[h0 + 8], vps[h0 + 8]);
            #pragma unroll
            for (int ni = 0; ni < 4; ni++) {
                ull pa = pack2(accr[mi][ni][0], accr[mi][ni][1]);
                ull pb = pack2(accr[mi][ni][2], accr[mi][ni][3]);
                ull ya = add2(pa, hxa);
                ull yb = add2(pb, hxb);
                if (mi < 2) {
                    // MUFU path (exact range)
                    float l0, l1;
                    unpack2(ya, l0, l1);
                    ull ta = pack2(tanh_fast(l0), tanh_fast(l1));
                    s2[ni] = fma2(va, ta, s2[ni]);
                    unpack2(yb, l0, l1);
                    ull tb = pack2(tanh_fast(l0), tanh_fast(l1));
                    s2[ni] = fma2(vb, tb, s2[ni]);
                } else {
                    // packed deg-7 odd poly: tanh(y) ~= y*(1 + u*(c3 + c5 u + c7 u^2))
                    ull ua = mul2(ya, ya);
                    ull qa = fma2(ua, C7, C5);
                    qa = fma2(ua, qa, C3);
                    ull wa = mul2(ya, ua);
                    ull ta = fma2(wa, qa, ya);
                    s2[ni] = fma2(va, ta, s2[ni]);

                    ull ub = mul2(yb, yb);
                    ull qb = fma2(ub, C7, C5);
                    qb = fma2(ub, qb, C3);
                    ull wb = mul2(yb, ub);
                    ull tb = fma2(wb, qb, yb);
                    s2[ni] = fma2(vb, tb, s2[ni]);
                }
            }
        }

        float pl[4][2];
        #pragma unroll
        for (int ni = 0; ni < 4; ni++) unpack2(s2[ni], pl[ni][0], pl[ni][1]);

        #pragma unroll
        for (int off = 4; off < 32; off <<= 1)
            #pragma unroll
            for (int ni = 0; ni < 4; ni++)
                #pragma unroll
                for (int j = 0; j < 2; j++)
                    pl[ni][j] += __shfl_xor_sync(0xffffffff, pl[ni][j], off);
        if (g == 0) {
            #pragma unroll
            for (int ni = 0; ni < 4; ni++)
                #pragma unroll
                for (int j = 0; j < 2; j++)
                    red[(nb + ni * 8 + 2 * tc + j) * 2 + wm] = pl[ni][j];
        }
        __syncthreads();
        if (t < 64) out[base + t] = red[t * 2] + red[t * 2 + 1];
    }
}

// ---------------------------------------------------------------------------
// Kernel 2: softmax over N=1024 per batch, in place.
// ---------------------------------------------------------------------------
__global__ void k_softmax(float* __restrict__ out) {
    __shared__ float red[256];
    int b = blockIdx.x;
    int t = threadIdx.x;
    float* row = out + b * 1024;
    float4 x = ((const float4*)row)[t];
    float m = fmaxf(fmaxf(x.x, x.y), fmaxf(x.z, x.w));
    red[t] = m;
    __syncthreads();
    for (int s = 128; s > 0; s >>= 1) {
        if (t < s) red[t] = fmaxf(red[t], red[t + s]);
        __syncthreads();
    }
    float M = red[0];
    __syncthreads();
    float e0 = __expf(x.x - M);
    float e1 = __expf(x.y - M);
    float e2 = __expf(x.z - M);
    float e3 = __expf(x.w - M);
    red[t] = e0 + e1 + e2 + e3;
    __syncthreads();
    for (int s = 128; s > 0; s >>= 1) {
        if (t < s) red[t] += red[t + s];
        __syncthreads();
    }
    float inv = 1.f / red[0];
    float4 r;
    r.x = e0 * inv; r.y = e1 * inv; r.z = e2 * inv; r.w = e3 * inv;
    ((float4*)row)[t] = r;
}

// ---------------------------------------------------------------------------
extern "C" void kernel_launch(void* const* d_in, const int* in_sizes, int n_in,
                              void* d_out, int out_size) {
    const float* nf     = (const float*)d_in[0];
    const float* Wemb   = (const float*)d_in[2];
    const float* bemb   = (const float*)d_in[3];
    const float* Wih    = (const float*)d_in[4];
    const float* bih    = (const float*)d_in[5];
    const float* bhh    = (const float*)d_in[7];
    const float* query  = (const float*)d_in[8];
    const float* Wattn  = (const float*)d_in[9];
    const float* vparam = (const float*)d_in[10];
    const float* Wval   = (const float*)d_in[11];
    const float* bval   = (const float*)d_in[12];
    float* out = (float*)d_out;

    static int smem_set = 0;
    const int smem_bytes = SM_WORDS * 4;
    if (!smem_set) {
        cudaFuncSetAttribute(k_logits, cudaFuncAttributeMaxDynamicSharedMemorySize,
                             smem_bytes);
        smem_set = 1;
    }

    k_hx<<<1, 512>>>(Wih, bih, bhh, query, Wval, bval, out);
    k_logits<<<GRID_LOGITS, 128, smem_bytes>>>(nf, Wemb, bemb, Wattn, vparam, out);
    k_softmax<<<64, 256>>>(out);
}